// round 13
// baseline (speedup 1.0000x reference)
#include <cuda_runtime.h>
#include <cstdint>
#include <math.h>

// ---------------------------------------------------------------------------
// GaussianSceneModel — R13: compaction pipeline (3 launches).
//   compact:  MUFU-free prefilters (square-form lidar test), warp-aggregated
//             append of surviving gaussian indices to dense lists.
//   process:  grid-stride over dense lists; exact R12 per-survivor arithmetic.
//   finalize: R9-proven 8px/thread v8 streaming + conditional self-clean;
//             also resets list counters (replay invariant).
// ---------------------------------------------------------------------------

#define W_IMG   1600
#define H_IMG   900
#define WL_IMG  1024
#define HL_IMG  128
#define CAM_PIX (W_IMG * H_IMG)          // 1,440,000
#define LID_PIX (WL_IMG * HL_IMG)        // 131,072
#define OFF_RGB   0
#define OFF_DEPTH (3 * CAM_PIX)
#define OFF_ALPHA (4 * CAM_PIX)
#define OFF_LD    (5 * CAM_PIX)
#define OFF_LA    (5 * CAM_PIX + LID_PIX)

#define FMIN_F ((float)(-0.4363323129985824))
#define FMAX_F ((float)(0.05235987755982988))
#define FRANGE_F ((float)(0.05235987755982988 + 0.4363323129985824))
#define TWO_PI_F ((float)(6.283185307179586))
#define SIN_FMIN_LO (-0.42261826f - 1e-4f)
#define SIN_FMAX_HI ( 0.05233596f + 1e-4f)
// widened square-form constants for the MUFU-free compact prefilter
#define SIN_LO_W (0.42261826f + 3e-4f)
#define SIN_HI_W (0.05233596f + 3e-4f)
#define NEAR_PLANE 1.0f
#define FAR_PLANE  100.0f
#define EPS 1e-8f
#define MAX_G 1000000

// Scratch accumulators. Zero-initialized at load; finalize self-cleans.
__device__ float4 g_cam4[CAM_PIX];        // (r*w, g*w, b*w, z*w)
__device__ float4 g_camA4[CAM_PIX / 4];   // sum w (scalar-indexed)
__device__ float4 g_lid4[LID_PIX / 2];    // pairs of (r*w, w)

// Compaction lists + counters (counters reset by finalize each call).
__device__ unsigned int g_cam_list[MAX_G];
__device__ unsigned int g_lid_list[MAX_G];
__device__ int g_cam_cnt = 0;
__device__ int g_lid_cnt = 0;

__device__ __forceinline__ void red_add_v4(float4* addr, float a, float b,
                                           float c, float d) {
    asm volatile("red.global.add.v4.f32 [%0], {%1, %2, %3, %4};"
                 :: "l"(addr), "f"(a), "f"(b), "f"(c), "f"(d) : "memory");
}
__device__ __forceinline__ void red_add_v2(float2* addr, float a, float b) {
    asm volatile("red.global.add.v2.f32 [%0], {%1, %2};"
                 :: "l"(addr), "f"(a), "f"(b) : "memory");
}
__device__ __forceinline__ void st_v8(float* p, float a0, float a1, float a2,
                                      float a3, float a4, float a5, float a6,
                                      float a7) {
    asm volatile("st.global.v8.f32 [%0], {%1,%2,%3,%4,%5,%6,%7,%8};"
                 :: "l"(p), "f"(a0), "f"(a1), "f"(a2), "f"(a3),
                    "f"(a4), "f"(a5), "f"(a6), "f"(a7) : "memory");
}
__device__ __forceinline__ void ld_v8(const float* p, float* r) {
    asm volatile("ld.global.v8.f32 {%0,%1,%2,%3,%4,%5,%6,%7}, [%8];"
                 : "=f"(r[0]), "=f"(r[1]), "=f"(r[2]), "=f"(r[3]),
                   "=f"(r[4]), "=f"(r[5]), "=f"(r[6]), "=f"(r[7])
                 : "l"(p));
}

__device__ void inv4x4(const float* m, float* invOut) {
    float inv[16];
    inv[0] = m[5]*m[10]*m[15] - m[5]*m[11]*m[14] - m[9]*m[6]*m[15] +
             m[9]*m[7]*m[14] + m[13]*m[6]*m[11] - m[13]*m[7]*m[10];
    inv[4] = -m[4]*m[10]*m[15] + m[4]*m[11]*m[14] + m[8]*m[6]*m[15] -
             m[8]*m[7]*m[14] - m[12]*m[6]*m[11] + m[12]*m[7]*m[10];
    inv[8] = m[4]*m[9]*m[15] - m[4]*m[11]*m[13] - m[8]*m[5]*m[15] +
             m[8]*m[7]*m[13] + m[12]*m[5]*m[11] - m[12]*m[7]*m[9];
    inv[12] = -m[4]*m[9]*m[14] + m[4]*m[10]*m[13] + m[8]*m[5]*m[14] -
              m[8]*m[6]*m[13] - m[12]*m[5]*m[10] + m[12]*m[6]*m[9];
    inv[1] = -m[1]*m[10]*m[15] + m[1]*m[11]*m[14] + m[9]*m[2]*m[15] -
             m[9]*m[3]*m[14] - m[13]*m[2]*m[11] + m[13]*m[3]*m[10];
    inv[5] = m[0]*m[10]*m[15] - m[0]*m[11]*m[14] - m[8]*m[2]*m[15] +
             m[8]*m[3]*m[14] + m[12]*m[2]*m[11] - m[12]*m[3]*m[10];
    inv[9] = -m[0]*m[9]*m[15] + m[0]*m[11]*m[13] + m[8]*m[1]*m[15] -
             m[8]*m[3]*m[13] - m[12]*m[1]*m[11] + m[12]*m[3]*m[9];
    inv[13] = m[0]*m[9]*m[14] - m[0]*m[10]*m[13] - m[8]*m[1]*m[14] +
              m[8]*m[2]*m[13] + m[12]*m[1]*m[10] - m[12]*m[2]*m[9];
    inv[2] = m[1]*m[6]*m[15] - m[1]*m[7]*m[14] - m[5]*m[2]*m[15] +
             m[5]*m[3]*m[14] + m[13]*m[2]*m[7] - m[13]*m[3]*m[6];
    inv[6] = -m[0]*m[6]*m[15] + m[0]*m[7]*m[14] + m[4]*m[2]*m[15] -
             m[4]*m[3]*m[14] - m[12]*m[2]*m[7] + m[12]*m[3]*m[6];
    inv[10] = m[0]*m[5]*m[15] - m[0]*m[7]*m[13] - m[4]*m[1]*m[15] +
              m[4]*m[3]*m[13] + m[12]*m[1]*m[7] - m[12]*m[3]*m[5];
    inv[14] = -m[0]*m[5]*m[14] + m[0]*m[6]*m[13] + m[4]*m[1]*m[14] -
              m[4]*m[2]*m[13] - m[12]*m[1]*m[6] + m[12]*m[2]*m[5];
    inv[3] = -m[1]*m[6]*m[11] + m[1]*m[7]*m[10] + m[5]*m[2]*m[11] -
             m[5]*m[3]*m[10] - m[9]*m[2]*m[7] + m[9]*m[3]*m[6];
    inv[7] = m[0]*m[6]*m[11] - m[0]*m[7]*m[10] - m[4]*m[2]*m[11] +
             m[4]*m[3]*m[10] + m[8]*m[2]*m[7] - m[8]*m[3]*m[6];
    inv[11] = -m[0]*m[5]*m[11] + m[0]*m[7]*m[9] + m[4]*m[1]*m[11] -
              m[4]*m[3]*m[9] - m[8]*m[1]*m[7] + m[8]*m[3]*m[5];
    inv[15] = m[0]*m[5]*m[10] - m[0]*m[6]*m[9] - m[4]*m[1]*m[10] +
              m[4]*m[2]*m[9] + m[8]*m[1]*m[6] - m[8]*m[2]*m[5];
    float det = m[0]*inv[0] + m[1]*inv[4] + m[2]*inv[8] + m[3]*inv[12];
    det = 1.0f / det;
    for (int i = 0; i < 16; i++) invOut[i] = inv[i] * det;
}

__device__ __forceinline__ void setup_params(const float* c2w, const float* Kmat,
                                             const float* l2w,
                                             float* sC, float* sL, float* sK) {
    if (threadIdx.x == 0) {
        float inv[16];
        inv4x4(c2w, inv);
        #pragma unroll
        for (int i = 0; i < 12; i++) sC[i] = inv[i];
        inv4x4(l2w, inv);
        #pragma unroll
        for (int i = 0; i < 12; i++) sL[i] = inv[i];
        float fx = Kmat[0], fy = Kmat[4], cx = Kmat[2], cy = Kmat[5];
        sK[0] = fx; sK[1] = fy; sK[2] = cx; sK[3] = cy;
        sK[4] = fmaxf(fabsf(-1.0f - cx), fabsf((float)W_IMG + 1.0f - cx)) + 2.0f;
        sK[5] = fmaxf(fabsf(-1.0f - cy), fabsf((float)H_IMG + 1.0f - cy)) + 2.0f;
    }
    __syncthreads();
}

__device__ __forceinline__ float sigmoid_fast(float x) {
    x = fminf(fmaxf(x, -20.0f), 20.0f);
    return __fdividef(1.0f, 1.0f + __expf(-x));
}
__device__ __forceinline__ float fast_atan2(float y, float x) {
    float ax = fabsf(x), ay = fabsf(y);
    float mx = fmaxf(ax, ay), mn = fminf(ax, ay);
    float t = __fdividef(mn, mx);
    float a = atanf(t);
    if (ay > ax) a = 1.5707963267948966f - a;
    if (x < 0.0f) a = 3.141592653589793f - a;
    return (y < 0.0f) ? -a : a;
}

// Warp-aggregated list append. Must be reached by ALL lanes of the warp.
__device__ __forceinline__ void warp_append(bool pred, unsigned int g,
                                            int* cnt, unsigned int* list) {
    unsigned int m = __ballot_sync(0xffffffffu, pred);
    if (m) {
        int lane = threadIdx.x & 31;
        int leader = __ffs(m) - 1;
        int base = 0;
        if (lane == leader) base = atomicAdd(cnt, __popc(m));
        base = __shfl_sync(0xffffffffu, base, leader);
        if (pred) list[base + __popc(m & ((1u << lane) - 1))] = g;
    }
}

// ---------------------------------------------------------------------------
// Pass 1: compact. MUFU-free predicates; 4 gaussians/thread.
// ---------------------------------------------------------------------------
__global__ void __launch_bounds__(256) compact_kernel(
        const float* __restrict__ means,
        const float* __restrict__ c2w,
        const float* __restrict__ Kmat,
        const float* __restrict__ l2w, int n) {
    __shared__ float sC[12], sL[12], sK[6];
    setup_params(c2w, Kmat, l2w, sC, sL, sK);

    const float LO2 = SIN_LO_W * SIN_LO_W;
    const float HI2 = SIN_HI_W * SIN_HI_W;

    int t = blockIdx.x * blockDim.x + threadIdx.x;
    int g0 = 4 * t;

    float mx[4], my[4], mz[4];
    bool valid[4];
    if (g0 + 3 < n) {
        const float4* m4 = (const float4*)means;
        float4 A = m4[3*t + 0];
        float4 B = m4[3*t + 1];
        float4 C = m4[3*t + 2];
        mx[0]=A.x; mx[1]=A.w; mx[2]=B.z; mx[3]=C.y;
        my[0]=A.y; my[1]=B.x; my[2]=B.w; my[3]=C.z;
        mz[0]=A.z; mz[1]=B.y; mz[2]=C.x; mz[3]=C.w;
        valid[0]=valid[1]=valid[2]=valid[3]=true;
    } else {
        #pragma unroll
        for (int k = 0; k < 4; k++) {
            int g = g0 + k;
            valid[k] = (g < n);
            mx[k] = valid[k] ? means[3*g+0] : 0.f;
            my[k] = valid[k] ? means[3*g+1] : 0.f;
            mz[k] = valid[k] ? means[3*g+2] : 0.f;
        }
    }

    #pragma unroll
    for (int k = 0; k < 4; k++) {
        // camera predicate (no MUFU)
        float xc = fmaf(sC[0], mx[k], fmaf(sC[1], my[k], fmaf(sC[2], mz[k], sC[3])));
        float yc = fmaf(sC[4], mx[k], fmaf(sC[5], my[k], fmaf(sC[6], mz[k], sC[7])));
        float zc = fmaf(sC[8], mx[k], fmaf(sC[9], my[k], fmaf(sC[10], mz[k], sC[11])));
        bool predC = valid[k] && zc > NEAR_PLANE && zc < FAR_PLANE &&
                     fabsf(__fmul_rn(sK[0], xc)) < sK[4] * zc &&
                     fabsf(__fmul_rn(sK[1], yc)) < sK[5] * zc;

        // lidar predicate, square form (no MUFU)
        float xl = fmaf(sL[0], mx[k], fmaf(sL[1], my[k], fmaf(sL[2], mz[k], sL[3])));
        float yl = fmaf(sL[4], mx[k], fmaf(sL[5], my[k], fmaf(sL[6], mz[k], sL[7])));
        float zl = fmaf(sL[8], mx[k], fmaf(sL[9], my[k], fmaf(sL[10], mz[k], sL[11])));
        float rr = fmaf(xl, xl, fmaf(yl, yl, zl * zl));
        float zz = zl * zl;
        bool up = (zl <= 0.0f) || (zz <= HI2 * rr);
        bool lo = (zl >= 0.0f) || (zz <= LO2 * rr);
        bool predL = valid[k] && rr > 0.999f && rr < 10002.0f && up && lo;

        warp_append(predC, (unsigned int)(g0 + k), &g_cam_cnt, g_cam_list);
        warp_append(predL, (unsigned int)(g0 + k), &g_lid_cnt, g_lid_list);
    }
}

// ---------------------------------------------------------------------------
// Pass 2: process dense survivor lists (grid-stride).
// Arithmetic identical to R12's per-survivor paths.
// ---------------------------------------------------------------------------
#define P2_BLOCKS 1184
__global__ void __launch_bounds__(256) process_kernel(
        const float* __restrict__ means,
        const float* __restrict__ sh,
        const float* __restrict__ opa_c,
        const float* __restrict__ opa_l,
        const float* __restrict__ c2w,
        const float* __restrict__ Kmat,
        const float* __restrict__ l2w) {
    __shared__ float sC[12], sL[12], sK[6];
    setup_params(c2w, Kmat, l2w, sC, sL, sK);

    int tid = blockIdx.x * blockDim.x + threadIdx.x;
    int stride = gridDim.x * blockDim.x;
    int nc = g_cam_cnt;
    int nl = g_lid_cnt;

    // ---- camera items ----
    for (int i = tid; i < nc; i += stride) {
        int g = g_cam_list[i];
        float mx = means[3*g], my = means[3*g+1], mz = means[3*g+2];
        float x = fmaf(sC[0], mx, fmaf(sC[1], my, fmaf(sC[2], mz, sC[3])));
        float y = fmaf(sC[4], mx, fmaf(sC[5], my, fmaf(sC[6], mz, sC[7])));
        float z = fmaf(sC[8], mx, fmaf(sC[9], my, fmaf(sC[10], mz, sC[11])));
        float tx = __fmul_rn(sK[0], x);
        float ty = __fmul_rn(sK[1], y);
        float u = __fadd_rn(__fdiv_rn(tx, z), sK[2]);
        float v = __fadd_rn(__fdiv_rn(ty, z), sK[3]);
        float u0 = floorf(u), v0 = floorf(v);
        float fu = __fsub_rn(u, u0), fv = __fsub_rn(v, v0);
        int u0i = (int)u0, v0i = (int)v0;
        if (u0i >= -1 && u0i < W_IMG && v0i >= -1 && v0i < H_IMG) {
            float oc = sigmoid_fast(opa_c[g]);
            float4 shv = *(const float4*)(sh + 48*g);
            float cr = sigmoid_fast(shv.x);
            float cg = sigmoid_fast(shv.y);
            float cb = sigmoid_fast(shv.z);
            float ofu = __fsub_rn(1.0f, fu), ofv = __fsub_rn(1.0f, fv);
            float cw[4] = { __fmul_rn(ofu, ofv), __fmul_rn(fu, ofv),
                            __fmul_rn(ofu, fv),  __fmul_rn(fu, fv) };
            #pragma unroll
            for (int c = 0; c < 4; c++) {
                int ui = u0i + (c & 1);
                int vi = v0i + (c >> 1);
                if (ui >= 0 && ui < W_IMG && vi >= 0 && vi < H_IMG) {
                    float ww = __fmul_rn(oc, cw[c]);
                    int pix = vi * W_IMG + ui;
                    red_add_v4(&g_cam4[pix],
                               __fmul_rn(cr, ww), __fmul_rn(cg, ww),
                               __fmul_rn(cb, ww), __fmul_rn(z, ww));
                    atomicAdd(&((float*)g_camA4)[pix], ww);
                }
            }
        }
    }

    // ---- lidar items ----
    for (int i = tid; i < nl; i += stride) {
        int g = g_lid_list[i];
        float mx = means[3*g], my = means[3*g+1], mz = means[3*g+2];
        float x = fmaf(sL[0], mx, fmaf(sL[1], my, fmaf(sL[2], mz, sL[3])));
        float y = fmaf(sL[4], mx, fmaf(sL[5], my, fmaf(sL[6], mz, sL[7])));
        float z = fmaf(sL[8], mx, fmaf(sL[9], my, fmaf(sL[10], mz, sL[11])));
        float rr = fmaf(x, x, fmaf(y, y, z * z));
        float rinv = __frsqrt_rn(rr);
        rinv = rinv * fmaf(-0.5f * rr, rinv * rinv, 1.5f);
        float r = rr * rinv;
        if (r > NEAR_PLANE && r < FAR_PLANE &&
            z >= SIN_FMIN_LO * r && z <= SIN_FMAX_HI * r) {
            float s = z * rinv;
            float el = asinf(s);
            if (el >= FMIN_F && el <= FMAX_F) {
                float az = fast_atan2(y, x);
                float uL = __fmul_rn(__fadd_rn(__fdiv_rn(az, TWO_PI_F), 0.5f),
                                     (float)WL_IMG);
                float vL = __fmul_rn(__fdiv_rn(__fsub_rn(FMAX_F, el), FRANGE_F),
                                     (float)(HL_IMG - 1));
                float u0 = floorf(uL), v0 = floorf(vL);
                float fu = __fsub_rn(uL, u0), fv = __fsub_rn(vL, v0);
                int u0i = (int)u0, v0i = (int)v0;
                float ol = sigmoid_fast(opa_l[g]);
                float ofu = __fsub_rn(1.0f, fu), ofv = __fsub_rn(1.0f, fv);
                float cw[4] = { __fmul_rn(ofu, ofv), __fmul_rn(fu, ofv),
                                __fmul_rn(ofu, fv),  __fmul_rn(fu, fv) };
                float2* lidf2 = (float2*)g_lid4;
                #pragma unroll
                for (int c = 0; c < 4; c++) {
                    int ui = (u0i + (c & 1)) & (WL_IMG - 1);
                    int vi = v0i + (c >> 1);
                    if (vi >= 0 && vi < HL_IMG) {
                        float ww = __fmul_rn(ol, cw[c]);
                        int pix = vi * WL_IMG + ui;
                        red_add_v2(&lidf2[pix], __fmul_rn(r, ww), ww);
                    }
                }
            }
        }
    }
}

// Finalize (R9-proven): 8 px/thread; conditional camera self-clean; resets
// the compaction counters for the next replay.
#define CAM_T8 (CAM_PIX / 8)   // 180,000
#define LID_T8 (LID_PIX / 8)   // 16,384
__global__ void __launch_bounds__(256) finalize_kernel(float* __restrict__ out) {
    int t = blockIdx.x * blockDim.x + threadIdx.x;
    const float4 z4 = make_float4(0.f, 0.f, 0.f, 0.f);
    if (t == 0) { g_cam_cnt = 0; g_lid_cnt = 0; }
    if (t < CAM_T8) {
        float w[8];
        ld_v8((const float*)g_camA4 + 8 * t, w);
        bool any = false;
        #pragma unroll
        for (int i = 0; i < 8; i++) any = any || (w[i] != 0.0f);

        float4 acc[8];
        #pragma unroll
        for (int i = 0; i < 8; i++) {
            acc[i] = (w[i] != 0.0f) ? g_cam4[8*t + i] : z4;
        }
        float rgb[24], d[8], a[8];
        #pragma unroll
        for (int i = 0; i < 8; i++) {
            float wpe = __fadd_rn(w[i], EPS);
            a[i] = fminf(fmaxf(w[i], 0.0f), 1.0f);
            float inv = __fdiv_rn(1.0f, wpe);
            rgb[3*i+0] = __fmul_rn(__fmul_rn(acc[i].x, inv), a[i]);
            rgb[3*i+1] = __fmul_rn(__fmul_rn(acc[i].y, inv), a[i]);
            rgb[3*i+2] = __fmul_rn(__fmul_rn(acc[i].z, inv), a[i]);
            d[i] = __fmul_rn(acc[i].w, inv);
        }
        float* rgbp = out + OFF_RGB + 24 * t;
        st_v8(rgbp + 0,  rgb[0],  rgb[1],  rgb[2],  rgb[3],
                         rgb[4],  rgb[5],  rgb[6],  rgb[7]);
        st_v8(rgbp + 8,  rgb[8],  rgb[9],  rgb[10], rgb[11],
                         rgb[12], rgb[13], rgb[14], rgb[15]);
        st_v8(rgbp + 16, rgb[16], rgb[17], rgb[18], rgb[19],
                         rgb[20], rgb[21], rgb[22], rgb[23]);
        st_v8(out + OFF_DEPTH + 8*t, d[0], d[1], d[2], d[3],
                                     d[4], d[5], d[6], d[7]);
        st_v8(out + OFF_ALPHA + 8*t, a[0], a[1], a[2], a[3],
                                     a[4], a[5], a[6], a[7]);
        if (any) {
            st_v8((float*)g_camA4 + 8*t, 0.f, 0.f, 0.f, 0.f,
                                         0.f, 0.f, 0.f, 0.f);
            #pragma unroll
            for (int i = 0; i < 8; i++)
                if (w[i] != 0.0f) g_cam4[8*t + i] = z4;
        }
    } else if (t < CAM_T8 + LID_T8) {
        int j = t - CAM_T8;
        float p[16];
        float* lp = (float*)g_lid4 + 16 * j;
        ld_v8(lp + 0, p + 0);
        ld_v8(lp + 8, p + 8);
        float d[8], w[8];
        #pragma unroll
        for (int i = 0; i < 8; i++) {
            d[i] = __fdiv_rn(p[2*i], __fadd_rn(p[2*i+1], EPS));
            w[i] = fminf(fmaxf(p[2*i+1], 0.0f), 1.0f);
        }
        st_v8(out + OFF_LD + 8*j, d[0], d[1], d[2], d[3],
                                  d[4], d[5], d[6], d[7]);
        st_v8(out + OFF_LA + 8*j, w[0], w[1], w[2], w[3],
                                  w[4], w[5], w[6], w[7]);
        st_v8(lp + 0, 0.f, 0.f, 0.f, 0.f, 0.f, 0.f, 0.f, 0.f);
        st_v8(lp + 8, 0.f, 0.f, 0.f, 0.f, 0.f, 0.f, 0.f, 0.f);
    }
}

extern "C" void kernel_launch(void* const* d_in, const int* in_sizes, int n_in,
                              void* d_out, int out_size) {
    const float* means = (const float*)d_in[0];
    const float* sh    = (const float*)d_in[3];
    const float* opa_c = (const float*)d_in[4];
    const float* opa_l = (const float*)d_in[5];
    const float* c2w   = (const float*)d_in[6];
    const float* K     = (const float*)d_in[7];
    const float* l2w   = (const float*)d_in[8];
    float* out = (float*)d_out;

    int n = in_sizes[0] / 3;

    int nt = (n + 3) / 4;
    compact_kernel<<<(nt + 255) / 256, 256>>>(means, c2w, K, l2w, n);
    process_kernel<<<P2_BLOCKS, 256>>>(means, sh, opa_c, opa_l, c2w, K, l2w);
    int tot = CAM_T8 + LID_T8;
    finalize_kernel<<<(tot + 255) / 256, 256>>>(out);
}

// round 14
// speedup vs baseline: 1.4479x; 1.4479x over previous
#include <cuda_runtime.h>
#include <cstdint>
#include <math.h>

// ---------------------------------------------------------------------------
// GaussianSceneModel — R14: modality-parallel pipeline.
// Camera chain (main stream):  splat_cam -> finalize_cam
// Lidar  chain (side stream):  splat_lid -> finalize_lid
// Fork/join via events inside graph capture -> parallel graph branches.
// All arithmetic identical to R12 (best-known-accurate). Zero-pass-free
// scratch invariant with conditional self-clean (R9-proven).
// ---------------------------------------------------------------------------

#define W_IMG   1600
#define H_IMG   900
#define WL_IMG  1024
#define HL_IMG  128
#define CAM_PIX (W_IMG * H_IMG)          // 1,440,000
#define LID_PIX (WL_IMG * HL_IMG)        // 131,072
#define OFF_RGB   0
#define OFF_DEPTH (3 * CAM_PIX)
#define OFF_ALPHA (4 * CAM_PIX)
#define OFF_LD    (5 * CAM_PIX)
#define OFF_LA    (5 * CAM_PIX + LID_PIX)

#define FMIN_F ((float)(-0.4363323129985824))
#define FMAX_F ((float)(0.05235987755982988))
#define FRANGE_F ((float)(0.05235987755982988 + 0.4363323129985824))
#define TWO_PI_F ((float)(6.283185307179586))
#define SIN_FMIN_LO (-0.42261826f - 1e-4f)
#define SIN_FMAX_HI ( 0.05233596f + 1e-4f)
#define NEAR_PLANE 1.0f
#define FAR_PLANE  100.0f
#define EPS 1e-8f

// Scratch accumulators. Zero-initialized at load; finalize self-cleans.
__device__ float4 g_cam4[CAM_PIX];        // (r*w, g*w, b*w, z*w)
__device__ float4 g_camA4[CAM_PIX / 4];   // sum w (scalar-indexed)
__device__ float4 g_lid4[LID_PIX / 2];    // pairs of (r*w, w)

__device__ __forceinline__ void red_add_v4(float4* addr, float a, float b,
                                           float c, float d) {
    asm volatile("red.global.add.v4.f32 [%0], {%1, %2, %3, %4};"
                 :: "l"(addr), "f"(a), "f"(b), "f"(c), "f"(d) : "memory");
}
__device__ __forceinline__ void red_add_v2(float2* addr, float a, float b) {
    asm volatile("red.global.add.v2.f32 [%0], {%1, %2};"
                 :: "l"(addr), "f"(a), "f"(b) : "memory");
}
__device__ __forceinline__ void st_v8(float* p, float a0, float a1, float a2,
                                      float a3, float a4, float a5, float a6,
                                      float a7) {
    asm volatile("st.global.v8.f32 [%0], {%1,%2,%3,%4,%5,%6,%7,%8};"
                 :: "l"(p), "f"(a0), "f"(a1), "f"(a2), "f"(a3),
                    "f"(a4), "f"(a5), "f"(a6), "f"(a7) : "memory");
}
__device__ __forceinline__ void ld_v8(const float* p, float* r) {
    asm volatile("ld.global.v8.f32 {%0,%1,%2,%3,%4,%5,%6,%7}, [%8];"
                 : "=f"(r[0]), "=f"(r[1]), "=f"(r[2]), "=f"(r[3]),
                   "=f"(r[4]), "=f"(r[5]), "=f"(r[6]), "=f"(r[7])
                 : "l"(p));
}

__device__ void inv4x4(const float* m, float* invOut) {
    float inv[16];
    inv[0] = m[5]*m[10]*m[15] - m[5]*m[11]*m[14] - m[9]*m[6]*m[15] +
             m[9]*m[7]*m[14] + m[13]*m[6]*m[11] - m[13]*m[7]*m[10];
    inv[4] = -m[4]*m[10]*m[15] + m[4]*m[11]*m[14] + m[8]*m[6]*m[15] -
             m[8]*m[7]*m[14] - m[12]*m[6]*m[11] + m[12]*m[7]*m[10];
    inv[8] = m[4]*m[9]*m[15] - m[4]*m[11]*m[13] - m[8]*m[5]*m[15] +
             m[8]*m[7]*m[13] + m[12]*m[5]*m[11] - m[12]*m[7]*m[9];
    inv[12] = -m[4]*m[9]*m[14] + m[4]*m[10]*m[13] + m[8]*m[5]*m[14] -
              m[8]*m[6]*m[13] - m[12]*m[5]*m[10] + m[12]*m[6]*m[9];
    inv[1] = -m[1]*m[10]*m[15] + m[1]*m[11]*m[14] + m[9]*m[2]*m[15] -
             m[9]*m[3]*m[14] - m[13]*m[2]*m[11] + m[13]*m[3]*m[10];
    inv[5] = m[0]*m[10]*m[15] - m[0]*m[11]*m[14] - m[8]*m[2]*m[15] +
             m[8]*m[3]*m[14] + m[12]*m[2]*m[11] - m[12]*m[3]*m[10];
    inv[9] = -m[0]*m[9]*m[15] + m[0]*m[11]*m[13] + m[8]*m[1]*m[15] -
             m[8]*m[3]*m[13] - m[12]*m[1]*m[11] + m[12]*m[3]*m[9];
    inv[13] = m[0]*m[9]*m[14] - m[0]*m[10]*m[13] - m[8]*m[1]*m[14] +
              m[8]*m[2]*m[13] + m[12]*m[1]*m[10] - m[12]*m[2]*m[9];
    inv[2] = m[1]*m[6]*m[15] - m[1]*m[7]*m[14] - m[5]*m[2]*m[15] +
             m[5]*m[3]*m[14] + m[13]*m[2]*m[7] - m[13]*m[3]*m[6];
    inv[6] = -m[0]*m[6]*m[15] + m[0]*m[7]*m[14] + m[4]*m[2]*m[15] -
             m[4]*m[3]*m[14] - m[12]*m[2]*m[7] + m[12]*m[3]*m[6];
    inv[10] = m[0]*m[5]*m[15] - m[0]*m[7]*m[13] - m[4]*m[1]*m[15] +
              m[4]*m[3]*m[13] + m[12]*m[1]*m[7] - m[12]*m[3]*m[5];
    inv[14] = -m[0]*m[5]*m[14] + m[0]*m[6]*m[13] + m[4]*m[1]*m[14] -
              m[4]*m[2]*m[13] - m[12]*m[1]*m[6] + m[12]*m[2]*m[5];
    inv[3] = -m[1]*m[6]*m[11] + m[1]*m[7]*m[10] + m[5]*m[2]*m[11] -
             m[5]*m[3]*m[10] - m[9]*m[2]*m[7] + m[9]*m[3]*m[6];
    inv[7] = m[0]*m[6]*m[11] - m[0]*m[7]*m[10] - m[4]*m[2]*m[11] +
             m[4]*m[3]*m[10] + m[8]*m[2]*m[7] - m[8]*m[3]*m[6];
    inv[11] = -m[0]*m[5]*m[11] + m[0]*m[7]*m[9] + m[4]*m[1]*m[11] -
              m[4]*m[3]*m[9] - m[8]*m[1]*m[7] + m[8]*m[3]*m[5];
    inv[15] = m[0]*m[5]*m[10] - m[0]*m[6]*m[9] - m[4]*m[1]*m[10] +
              m[4]*m[2]*m[9] + m[8]*m[1]*m[6] - m[8]*m[2]*m[5];
    float det = m[0]*inv[0] + m[1]*inv[4] + m[2]*inv[8] + m[3]*inv[12];
    det = 1.0f / det;
    for (int i = 0; i < 16; i++) invOut[i] = inv[i] * det;
}

__device__ __forceinline__ float sigmoid_fast(float x) {
    x = fminf(fmaxf(x, -20.0f), 20.0f);
    return __fdividef(1.0f, 1.0f + __expf(-x));
}
__device__ __forceinline__ float fast_atan2(float y, float x) {
    float ax = fabsf(x), ay = fabsf(y);
    float mx = fmaxf(ax, ay), mn = fminf(ax, ay);
    float t = __fdividef(mn, mx);
    float a = atanf(t);
    if (ay > ax) a = 1.5707963267948966f - a;
    if (x < 0.0f) a = 3.141592653589793f - a;
    return (y < 0.0f) ? -a : a;
}

// ---------------------------------------------------------------------------
// Camera splat (4 gaussians/thread).
// ---------------------------------------------------------------------------
__global__ void __launch_bounds__(256) splat_cam_kernel(
        const float* __restrict__ means,
        const float* __restrict__ sh,
        const float* __restrict__ opa_c,
        const float* __restrict__ c2w,
        const float* __restrict__ Kmat, int n) {
    __shared__ float sC[12], sK[6];
    if (threadIdx.x == 0) {
        float inv[16];
        inv4x4(c2w, inv);
        #pragma unroll
        for (int i = 0; i < 12; i++) sC[i] = inv[i];
        float fx = Kmat[0], fy = Kmat[4], cx = Kmat[2], cy = Kmat[5];
        sK[0] = fx; sK[1] = fy; sK[2] = cx; sK[3] = cy;
        sK[4] = fmaxf(fabsf(-1.0f - cx), fabsf((float)W_IMG + 1.0f - cx)) + 2.0f;
        sK[5] = fmaxf(fabsf(-1.0f - cy), fabsf((float)H_IMG + 1.0f - cy)) + 2.0f;
    }
    __syncthreads();

    int t = blockIdx.x * blockDim.x + threadIdx.x;
    int g0 = 4 * t;
    if (g0 >= n) return;

    float mx[4], my[4], mz[4];
    int cnt = 4;
    if (g0 + 3 < n) {
        const float4* m4 = (const float4*)means;
        float4 A = m4[3*t + 0];
        float4 B = m4[3*t + 1];
        float4 C = m4[3*t + 2];
        mx[0]=A.x; mx[1]=A.w; mx[2]=B.z; mx[3]=C.y;
        my[0]=A.y; my[1]=B.x; my[2]=B.w; my[3]=C.z;
        mz[0]=A.z; mz[1]=B.y; mz[2]=C.x; mz[3]=C.w;
    } else {
        cnt = n - g0;
        for (int k = 0; k < cnt; k++) {
            int g = g0 + k;
            mx[k] = means[3*g]; my[k] = means[3*g+1]; mz[k] = means[3*g+2];
        }
    }

    for (int k = 0; k < cnt; k++) {
        int g = g0 + k;
        float x = fmaf(sC[0], mx[k], fmaf(sC[1], my[k], fmaf(sC[2], mz[k], sC[3])));
        float y = fmaf(sC[4], mx[k], fmaf(sC[5], my[k], fmaf(sC[6], mz[k], sC[7])));
        float z = fmaf(sC[8], mx[k], fmaf(sC[9], my[k], fmaf(sC[10], mz[k], sC[11])));
        if (z > NEAR_PLANE && z < FAR_PLANE) {
            float tx = __fmul_rn(sK[0], x);
            float ty = __fmul_rn(sK[1], y);
            if (fabsf(tx) < sK[4] * z && fabsf(ty) < sK[5] * z) {
                float u = __fadd_rn(__fdiv_rn(tx, z), sK[2]);
                float v = __fadd_rn(__fdiv_rn(ty, z), sK[3]);
                float u0 = floorf(u), v0 = floorf(v);
                float fu = __fsub_rn(u, u0), fv = __fsub_rn(v, v0);
                int u0i = (int)u0, v0i = (int)v0;
                if (u0i >= -1 && u0i < W_IMG && v0i >= -1 && v0i < H_IMG) {
                    float oc = sigmoid_fast(opa_c[g]);
                    float4 shv = *(const float4*)(sh + 48*g);
                    float cr = sigmoid_fast(shv.x);
                    float cg = sigmoid_fast(shv.y);
                    float cb = sigmoid_fast(shv.z);
                    float ofu = __fsub_rn(1.0f, fu), ofv = __fsub_rn(1.0f, fv);
                    float cw[4] = { __fmul_rn(ofu, ofv), __fmul_rn(fu, ofv),
                                    __fmul_rn(ofu, fv),  __fmul_rn(fu, fv) };
                    #pragma unroll
                    for (int c = 0; c < 4; c++) {
                        int ui = u0i + (c & 1);
                        int vi = v0i + (c >> 1);
                        if (ui >= 0 && ui < W_IMG && vi >= 0 && vi < H_IMG) {
                            float ww = __fmul_rn(oc, cw[c]);
                            int pix = vi * W_IMG + ui;
                            red_add_v4(&g_cam4[pix],
                                       __fmul_rn(cr, ww), __fmul_rn(cg, ww),
                                       __fmul_rn(cb, ww), __fmul_rn(z, ww));
                            atomicAdd(&((float*)g_camA4)[pix], ww);
                        }
                    }
                }
            }
        }
    }
}

// ---------------------------------------------------------------------------
// Lidar splat (4 gaussians/thread), R12 fast transcendentals.
// ---------------------------------------------------------------------------
__global__ void __launch_bounds__(256) splat_lid_kernel(
        const float* __restrict__ means,
        const float* __restrict__ opa_l,
        const float* __restrict__ l2w, int n) {
    __shared__ float sL[12];
    if (threadIdx.x == 0) {
        float inv[16];
        inv4x4(l2w, inv);
        #pragma unroll
        for (int i = 0; i < 12; i++) sL[i] = inv[i];
    }
    __syncthreads();

    int t = blockIdx.x * blockDim.x + threadIdx.x;
    int g0 = 4 * t;
    if (g0 >= n) return;

    float mx[4], my[4], mz[4];
    int cnt = 4;
    if (g0 + 3 < n) {
        const float4* m4 = (const float4*)means;
        float4 A = m4[3*t + 0];
        float4 B = m4[3*t + 1];
        float4 C = m4[3*t + 2];
        mx[0]=A.x; mx[1]=A.w; mx[2]=B.z; mx[3]=C.y;
        my[0]=A.y; my[1]=B.x; my[2]=B.w; my[3]=C.z;
        mz[0]=A.z; mz[1]=B.y; mz[2]=C.x; mz[3]=C.w;
    } else {
        cnt = n - g0;
        for (int k = 0; k < cnt; k++) {
            int g = g0 + k;
            mx[k] = means[3*g]; my[k] = means[3*g+1]; mz[k] = means[3*g+2];
        }
    }

    for (int k = 0; k < cnt; k++) {
        int g = g0 + k;
        float x = fmaf(sL[0], mx[k], fmaf(sL[1], my[k], fmaf(sL[2], mz[k], sL[3])));
        float y = fmaf(sL[4], mx[k], fmaf(sL[5], my[k], fmaf(sL[6], mz[k], sL[7])));
        float z = fmaf(sL[8], mx[k], fmaf(sL[9], my[k], fmaf(sL[10], mz[k], sL[11])));
        float rr = fmaf(x, x, fmaf(y, y, z * z));
        float rinv = __frsqrt_rn(rr);
        rinv = rinv * fmaf(-0.5f * rr, rinv * rinv, 1.5f);
        float r = rr * rinv;
        if (r > NEAR_PLANE && r < FAR_PLANE &&
            z >= SIN_FMIN_LO * r && z <= SIN_FMAX_HI * r) {
            float s = z * rinv;
            float el = asinf(s);
            if (el >= FMIN_F && el <= FMAX_F) {
                float az = fast_atan2(y, x);
                float uL = __fmul_rn(__fadd_rn(__fdiv_rn(az, TWO_PI_F), 0.5f),
                                     (float)WL_IMG);
                float vL = __fmul_rn(__fdiv_rn(__fsub_rn(FMAX_F, el), FRANGE_F),
                                     (float)(HL_IMG - 1));
                float u0 = floorf(uL), v0 = floorf(vL);
                float fu = __fsub_rn(uL, u0), fv = __fsub_rn(vL, v0);
                int u0i = (int)u0, v0i = (int)v0;
                float ol = sigmoid_fast(opa_l[g]);
                float ofu = __fsub_rn(1.0f, fu), ofv = __fsub_rn(1.0f, fv);
                float cw[4] = { __fmul_rn(ofu, ofv), __fmul_rn(fu, ofv),
                                __fmul_rn(ofu, fv),  __fmul_rn(fu, fv) };
                float2* lidf2 = (float2*)g_lid4;
                #pragma unroll
                for (int c = 0; c < 4; c++) {
                    int ui = (u0i + (c & 1)) & (WL_IMG - 1);
                    int vi = v0i + (c >> 1);
                    if (vi >= 0 && vi < HL_IMG) {
                        float ww = __fmul_rn(ol, cw[c]);
                        int pix = vi * WL_IMG + ui;
                        red_add_v2(&lidf2[pix], __fmul_rn(r, ww), ww);
                    }
                }
            }
        }
    }
}

// ---------------------------------------------------------------------------
// Camera finalize (R9-proven, 8 px/thread, conditional self-clean).
// ---------------------------------------------------------------------------
#define CAM_T8 (CAM_PIX / 8)   // 180,000
__global__ void __launch_bounds__(256) finalize_cam_kernel(float* __restrict__ out) {
    int t = blockIdx.x * blockDim.x + threadIdx.x;
    if (t >= CAM_T8) return;
    const float4 z4 = make_float4(0.f, 0.f, 0.f, 0.f);
    float w[8];
    ld_v8((const float*)g_camA4 + 8 * t, w);
    bool any = false;
    #pragma unroll
    for (int i = 0; i < 8; i++) any = any || (w[i] != 0.0f);

    float4 acc[8];
    #pragma unroll
    for (int i = 0; i < 8; i++) {
        acc[i] = (w[i] != 0.0f) ? g_cam4[8*t + i] : z4;
    }
    float rgb[24], d[8], a[8];
    #pragma unroll
    for (int i = 0; i < 8; i++) {
        float wpe = __fadd_rn(w[i], EPS);
        a[i] = fminf(fmaxf(w[i], 0.0f), 1.0f);
        float inv = __fdiv_rn(1.0f, wpe);
        rgb[3*i+0] = __fmul_rn(__fmul_rn(acc[i].x, inv), a[i]);
        rgb[3*i+1] = __fmul_rn(__fmul_rn(acc[i].y, inv), a[i]);
        rgb[3*i+2] = __fmul_rn(__fmul_rn(acc[i].z, inv), a[i]);
        d[i] = __fmul_rn(acc[i].w, inv);
    }
    float* rgbp = out + OFF_RGB + 24 * t;
    st_v8(rgbp + 0,  rgb[0],  rgb[1],  rgb[2],  rgb[3],
                     rgb[4],  rgb[5],  rgb[6],  rgb[7]);
    st_v8(rgbp + 8,  rgb[8],  rgb[9],  rgb[10], rgb[11],
                     rgb[12], rgb[13], rgb[14], rgb[15]);
    st_v8(rgbp + 16, rgb[16], rgb[17], rgb[18], rgb[19],
                     rgb[20], rgb[21], rgb[22], rgb[23]);
    st_v8(out + OFF_DEPTH + 8*t, d[0], d[1], d[2], d[3],
                                 d[4], d[5], d[6], d[7]);
    st_v8(out + OFF_ALPHA + 8*t, a[0], a[1], a[2], a[3],
                                 a[4], a[5], a[6], a[7]);
    if (any) {
        st_v8((float*)g_camA4 + 8*t, 0.f, 0.f, 0.f, 0.f,
                                     0.f, 0.f, 0.f, 0.f);
        #pragma unroll
        for (int i = 0; i < 8; i++)
            if (w[i] != 0.0f) g_cam4[8*t + i] = z4;
    }
}

// ---------------------------------------------------------------------------
// Lidar finalize (8 px/thread, unconditional self-clean).
// ---------------------------------------------------------------------------
#define LID_T8 (LID_PIX / 8)   // 16,384
__global__ void __launch_bounds__(256) finalize_lid_kernel(float* __restrict__ out) {
    int j = blockIdx.x * blockDim.x + threadIdx.x;
    if (j >= LID_T8) return;
    float p[16];
    float* lp = (float*)g_lid4 + 16 * j;
    ld_v8(lp + 0, p + 0);
    ld_v8(lp + 8, p + 8);
    float d[8], w[8];
    #pragma unroll
    for (int i = 0; i < 8; i++) {
        d[i] = __fdiv_rn(p[2*i], __fadd_rn(p[2*i+1], EPS));
        w[i] = fminf(fmaxf(p[2*i+1], 0.0f), 1.0f);
    }
    st_v8(out + OFF_LD + 8*j, d[0], d[1], d[2], d[3],
                              d[4], d[5], d[6], d[7]);
    st_v8(out + OFF_LA + 8*j, w[0], w[1], w[2], w[3],
                              w[4], w[5], w[6], w[7]);
    st_v8(lp + 0, 0.f, 0.f, 0.f, 0.f, 0.f, 0.f, 0.f, 0.f);
    st_v8(lp + 8, 0.f, 0.f, 0.f, 0.f, 0.f, 0.f, 0.f, 0.f);
}

extern "C" void kernel_launch(void* const* d_in, const int* in_sizes, int n_in,
                              void* d_out, int out_size) {
    const float* means = (const float*)d_in[0];
    const float* sh    = (const float*)d_in[3];
    const float* opa_c = (const float*)d_in[4];
    const float* opa_l = (const float*)d_in[5];
    const float* c2w   = (const float*)d_in[6];
    const float* K     = (const float*)d_in[7];
    const float* l2w   = (const float*)d_in[8];
    float* out = (float*)d_out;

    int n = in_sizes[0] / 3;
    int nt = (n + 3) / 4;
    int splat_blocks = (nt + 255) / 256;

    // Fork a side stream for the (independent) lidar chain. Objects are
    // created per call and intentionally not destroyed (cannot destroy a
    // stream that is part of an active capture); kernel_launch is invoked
    // only a handful of times, and no device memory is involved.
    cudaStream_t s2;
    cudaStreamCreateWithFlags(&s2, cudaStreamNonBlocking);
    cudaEvent_t eFork, eJoin;
    cudaEventCreateWithFlags(&eFork, cudaEventDisableTiming);
    cudaEventCreateWithFlags(&eJoin, cudaEventDisableTiming);

    cudaEventRecord(eFork, 0);
    cudaStreamWaitEvent(s2, eFork, 0);

    // Lidar chain on side stream.
    splat_lid_kernel<<<splat_blocks, 256, 0, s2>>>(means, opa_l, l2w, n);
    finalize_lid_kernel<<<(LID_T8 + 255) / 256, 256, 0, s2>>>(out);
    cudaEventRecord(eJoin, s2);

    // Camera chain on main (capture) stream.
    splat_cam_kernel<<<splat_blocks, 256>>>(means, sh, opa_c, c2w, K, n);
    finalize_cam_kernel<<<(CAM_T8 + 255) / 256, 256>>>(out);

    // Join.
    cudaStreamWaitEvent(0, eJoin, 0);
}

// round 15
// speedup vs baseline: 1.6163x; 1.1163x over previous
#include <cuda_runtime.h>
#include <cstdint>
#include <math.h>

// ---------------------------------------------------------------------------
// GaussianSceneModel — R15: R12 structure + 1-gaussian/thread splat with
// high occupancy (launch_bounds cap). Zero-pass-free scratch invariant,
// conditional self-clean finalize (R9-proven). Exact-IEEE camera path.
// ---------------------------------------------------------------------------

#define W_IMG   1600
#define H_IMG   900
#define WL_IMG  1024
#define HL_IMG  128
#define CAM_PIX (W_IMG * H_IMG)          // 1,440,000
#define LID_PIX (WL_IMG * HL_IMG)        // 131,072
#define OFF_RGB   0
#define OFF_DEPTH (3 * CAM_PIX)
#define OFF_ALPHA (4 * CAM_PIX)
#define OFF_LD    (5 * CAM_PIX)
#define OFF_LA    (5 * CAM_PIX + LID_PIX)

#define FMIN_F ((float)(-0.4363323129985824))
#define FMAX_F ((float)(0.05235987755982988))
#define FRANGE_F ((float)(0.05235987755982988 + 0.4363323129985824))
#define TWO_PI_F ((float)(6.283185307179586))
#define SIN_FMIN_LO (-0.42261826f - 1e-4f)
#define SIN_FMAX_HI ( 0.05233596f + 1e-4f)
#define NEAR_PLANE 1.0f
#define FAR_PLANE  100.0f
#define EPS 1e-8f

// Scratch accumulators. Zero-initialized at load; finalize self-cleans.
__device__ float4 g_cam4[CAM_PIX];        // (r*w, g*w, b*w, z*w)
__device__ float4 g_camA4[CAM_PIX / 4];   // sum w (scalar-indexed)
__device__ float4 g_lid4[LID_PIX / 2];    // pairs of (r*w, w)

__device__ __forceinline__ void red_add_v4(float4* addr, float a, float b,
                                           float c, float d) {
    asm volatile("red.global.add.v4.f32 [%0], {%1, %2, %3, %4};"
                 :: "l"(addr), "f"(a), "f"(b), "f"(c), "f"(d) : "memory");
}
__device__ __forceinline__ void red_add_v2(float2* addr, float a, float b) {
    asm volatile("red.global.add.v2.f32 [%0], {%1, %2};"
                 :: "l"(addr), "f"(a), "f"(b) : "memory");
}
__device__ __forceinline__ void st_v8(float* p, float a0, float a1, float a2,
                                      float a3, float a4, float a5, float a6,
                                      float a7) {
    asm volatile("st.global.v8.f32 [%0], {%1,%2,%3,%4,%5,%6,%7,%8};"
                 :: "l"(p), "f"(a0), "f"(a1), "f"(a2), "f"(a3),
                    "f"(a4), "f"(a5), "f"(a6), "f"(a7) : "memory");
}
__device__ __forceinline__ void ld_v8(const float* p, float* r) {
    asm volatile("ld.global.v8.f32 {%0,%1,%2,%3,%4,%5,%6,%7}, [%8];"
                 : "=f"(r[0]), "=f"(r[1]), "=f"(r[2]), "=f"(r[3]),
                   "=f"(r[4]), "=f"(r[5]), "=f"(r[6]), "=f"(r[7])
                 : "l"(p));
}

__device__ void inv4x4(const float* m, float* invOut) {
    float inv[16];
    inv[0] = m[5]*m[10]*m[15] - m[5]*m[11]*m[14] - m[9]*m[6]*m[15] +
             m[9]*m[7]*m[14] + m[13]*m[6]*m[11] - m[13]*m[7]*m[10];
    inv[4] = -m[4]*m[10]*m[15] + m[4]*m[11]*m[14] + m[8]*m[6]*m[15] -
             m[8]*m[7]*m[14] - m[12]*m[6]*m[11] + m[12]*m[7]*m[10];
    inv[8] = m[4]*m[9]*m[15] - m[4]*m[11]*m[13] - m[8]*m[5]*m[15] +
             m[8]*m[7]*m[13] + m[12]*m[5]*m[11] - m[12]*m[7]*m[9];
    inv[12] = -m[4]*m[9]*m[14] + m[4]*m[10]*m[13] + m[8]*m[5]*m[14] -
              m[8]*m[6]*m[13] - m[12]*m[5]*m[10] + m[12]*m[6]*m[9];
    inv[1] = -m[1]*m[10]*m[15] + m[1]*m[11]*m[14] + m[9]*m[2]*m[15] -
             m[9]*m[3]*m[14] - m[13]*m[2]*m[11] + m[13]*m[3]*m[10];
    inv[5] = m[0]*m[10]*m[15] - m[0]*m[11]*m[14] - m[8]*m[2]*m[15] +
             m[8]*m[3]*m[14] + m[12]*m[2]*m[11] - m[12]*m[3]*m[10];
    inv[9] = -m[0]*m[9]*m[15] + m[0]*m[11]*m[13] + m[8]*m[1]*m[15] -
             m[8]*m[3]*m[13] - m[12]*m[1]*m[11] + m[12]*m[3]*m[9];
    inv[13] = m[0]*m[9]*m[14] - m[0]*m[10]*m[13] - m[8]*m[1]*m[14] +
              m[8]*m[2]*m[13] + m[12]*m[1]*m[10] - m[12]*m[2]*m[9];
    inv[2] = m[1]*m[6]*m[15] - m[1]*m[7]*m[14] - m[5]*m[2]*m[15] +
             m[5]*m[3]*m[14] + m[13]*m[2]*m[7] - m[13]*m[3]*m[6];
    inv[6] = -m[0]*m[6]*m[15] + m[0]*m[7]*m[14] + m[4]*m[2]*m[15] -
             m[4]*m[3]*m[14] - m[12]*m[2]*m[7] + m[12]*m[3]*m[6];
    inv[10] = m[0]*m[5]*m[15] - m[0]*m[7]*m[13] - m[4]*m[1]*m[15] +
              m[4]*m[3]*m[13] + m[12]*m[1]*m[7] - m[12]*m[3]*m[5];
    inv[14] = -m[0]*m[5]*m[14] + m[0]*m[6]*m[13] + m[4]*m[1]*m[14] -
              m[4]*m[2]*m[13] - m[12]*m[1]*m[6] + m[12]*m[2]*m[5];
    inv[3] = -m[1]*m[6]*m[11] + m[1]*m[7]*m[10] + m[5]*m[2]*m[11] -
             m[5]*m[3]*m[10] - m[9]*m[2]*m[7] + m[9]*m[3]*m[6];
    inv[7] = m[0]*m[6]*m[11] - m[0]*m[7]*m[10] - m[4]*m[2]*m[11] +
             m[4]*m[3]*m[10] + m[8]*m[2]*m[7] - m[8]*m[3]*m[6];
    inv[11] = -m[0]*m[5]*m[11] + m[0]*m[7]*m[9] + m[4]*m[1]*m[11] -
              m[4]*m[3]*m[9] - m[8]*m[1]*m[7] + m[8]*m[3]*m[5];
    inv[15] = m[0]*m[5]*m[10] - m[0]*m[6]*m[9] - m[4]*m[1]*m[10] +
              m[4]*m[2]*m[9] + m[8]*m[1]*m[6] - m[8]*m[2]*m[5];
    float det = m[0]*inv[0] + m[1]*inv[4] + m[2]*inv[8] + m[3]*inv[12];
    det = 1.0f / det;
    for (int i = 0; i < 16; i++) invOut[i] = inv[i] * det;
}

__device__ __forceinline__ float sigmoid_fast(float x) {
    x = fminf(fmaxf(x, -20.0f), 20.0f);
    return __fdividef(1.0f, 1.0f + __expf(-x));
}
__device__ __forceinline__ float fast_atan2(float y, float x) {
    float ax = fabsf(x), ay = fabsf(y);
    float mx = fmaxf(ax, ay), mn = fminf(ax, ay);
    float t = __fdividef(mn, mx);
    float a = atanf(t);
    if (ay > ax) a = 1.5707963267948966f - a;
    if (x < 0.0f) a = 3.141592653589793f - a;
    return (y < 0.0f) ? -a : a;
}

// ---------------------------------------------------------------------------
// Fused splat: 1 gaussian/thread, high occupancy.
// ---------------------------------------------------------------------------
__global__ void __launch_bounds__(256, 8) splat_kernel(
        const float* __restrict__ means,
        const float* __restrict__ sh,
        const float* __restrict__ opa_c,
        const float* __restrict__ opa_l,
        const float* __restrict__ c2w,
        const float* __restrict__ Kmat,
        const float* __restrict__ l2w, int n) {
    __shared__ float sC[12], sL[12], sK[6];
    if (threadIdx.x == 0) {
        float inv[16];
        inv4x4(c2w, inv);
        #pragma unroll
        for (int i = 0; i < 12; i++) sC[i] = inv[i];
        inv4x4(l2w, inv);
        #pragma unroll
        for (int i = 0; i < 12; i++) sL[i] = inv[i];
        float fx = Kmat[0], fy = Kmat[4], cx = Kmat[2], cy = Kmat[5];
        sK[0] = fx; sK[1] = fy; sK[2] = cx; sK[3] = cy;
        sK[4] = fmaxf(fabsf(-1.0f - cx), fabsf((float)W_IMG + 1.0f - cx)) + 2.0f;
        sK[5] = fmaxf(fabsf(-1.0f - cy), fabsf((float)H_IMG + 1.0f - cy)) + 2.0f;
    }
    __syncthreads();

    int g = blockIdx.x * blockDim.x + threadIdx.x;
    if (g >= n) return;

    const float mx = means[3*g + 0];
    const float my = means[3*g + 1];
    const float mz = means[3*g + 2];

    // ---------------- camera (exact-IEEE projection) ----------------
    {
        float x = fmaf(sC[0], mx, fmaf(sC[1], my, fmaf(sC[2], mz, sC[3])));
        float y = fmaf(sC[4], mx, fmaf(sC[5], my, fmaf(sC[6], mz, sC[7])));
        float z = fmaf(sC[8], mx, fmaf(sC[9], my, fmaf(sC[10], mz, sC[11])));
        if (z > NEAR_PLANE && z < FAR_PLANE) {
            float tx = __fmul_rn(sK[0], x);
            float ty = __fmul_rn(sK[1], y);
            if (fabsf(tx) < sK[4] * z && fabsf(ty) < sK[5] * z) {
                float u = __fadd_rn(__fdiv_rn(tx, z), sK[2]);
                float v = __fadd_rn(__fdiv_rn(ty, z), sK[3]);
                float u0 = floorf(u), v0 = floorf(v);
                float fu = __fsub_rn(u, u0), fv = __fsub_rn(v, v0);
                int u0i = (int)u0, v0i = (int)v0;
                if (u0i >= -1 && u0i < W_IMG && v0i >= -1 && v0i < H_IMG) {
                    float oc = sigmoid_fast(opa_c[g]);
                    float4 shv = *(const float4*)(sh + 48*g);
                    float cr = sigmoid_fast(shv.x);
                    float cg = sigmoid_fast(shv.y);
                    float cb = sigmoid_fast(shv.z);
                    float ofu = __fsub_rn(1.0f, fu), ofv = __fsub_rn(1.0f, fv);
                    float cw[4] = { __fmul_rn(ofu, ofv), __fmul_rn(fu, ofv),
                                    __fmul_rn(ofu, fv),  __fmul_rn(fu, fv) };
                    #pragma unroll
                    for (int c = 0; c < 4; c++) {
                        int ui = u0i + (c & 1);
                        int vi = v0i + (c >> 1);
                        if (ui >= 0 && ui < W_IMG && vi >= 0 && vi < H_IMG) {
                            float ww = __fmul_rn(oc, cw[c]);
                            int pix = vi * W_IMG + ui;
                            red_add_v4(&g_cam4[pix],
                                       __fmul_rn(cr, ww), __fmul_rn(cg, ww),
                                       __fmul_rn(cb, ww), __fmul_rn(z, ww));
                            atomicAdd(&((float*)g_camA4)[pix], ww);
                        }
                    }
                }
            }
        }
    }

    // ---------------- lidar (R12 fast transcendentals) ----------------
    {
        float x = fmaf(sL[0], mx, fmaf(sL[1], my, fmaf(sL[2], mz, sL[3])));
        float y = fmaf(sL[4], mx, fmaf(sL[5], my, fmaf(sL[6], mz, sL[7])));
        float z = fmaf(sL[8], mx, fmaf(sL[9], my, fmaf(sL[10], mz, sL[11])));
        float rr = fmaf(x, x, fmaf(y, y, z * z));
        float rinv = __frsqrt_rn(rr);
        rinv = rinv * fmaf(-0.5f * rr, rinv * rinv, 1.5f);
        float r = rr * rinv;
        if (r > NEAR_PLANE && r < FAR_PLANE &&
            z >= SIN_FMIN_LO * r && z <= SIN_FMAX_HI * r) {
            float s = z * rinv;
            float el = asinf(s);
            if (el >= FMIN_F && el <= FMAX_F) {
                float az = fast_atan2(y, x);
                float uL = __fmul_rn(__fadd_rn(__fdiv_rn(az, TWO_PI_F), 0.5f),
                                     (float)WL_IMG);
                float vL = __fmul_rn(__fdiv_rn(__fsub_rn(FMAX_F, el), FRANGE_F),
                                     (float)(HL_IMG - 1));
                float u0 = floorf(uL), v0 = floorf(vL);
                float fu = __fsub_rn(uL, u0), fv = __fsub_rn(vL, v0);
                int u0i = (int)u0, v0i = (int)v0;
                float ol = sigmoid_fast(opa_l[g]);
                float ofu = __fsub_rn(1.0f, fu), ofv = __fsub_rn(1.0f, fv);
                float cw[4] = { __fmul_rn(ofu, ofv), __fmul_rn(fu, ofv),
                                __fmul_rn(ofu, fv),  __fmul_rn(fu, fv) };
                float2* lidf2 = (float2*)g_lid4;
                #pragma unroll
                for (int c = 0; c < 4; c++) {
                    int ui = (u0i + (c & 1)) & (WL_IMG - 1);
                    int vi = v0i + (c >> 1);
                    if (vi >= 0 && vi < HL_IMG) {
                        float ww = __fmul_rn(ol, cw[c]);
                        int pix = vi * WL_IMG + ui;
                        red_add_v2(&lidf2[pix], __fmul_rn(r, ww), ww);
                    }
                }
            }
        }
    }
}

// Finalize (R9-proven): 8 px/thread; conditional camera self-clean.
#define CAM_T8 (CAM_PIX / 8)   // 180,000
#define LID_T8 (LID_PIX / 8)   // 16,384
__global__ void __launch_bounds__(256) finalize_kernel(float* __restrict__ out) {
    int t = blockIdx.x * blockDim.x + threadIdx.x;
    const float4 z4 = make_float4(0.f, 0.f, 0.f, 0.f);
    if (t < CAM_T8) {
        float w[8];
        ld_v8((const float*)g_camA4 + 8 * t, w);
        bool any = false;
        #pragma unroll
        for (int i = 0; i < 8; i++) any = any || (w[i] != 0.0f);

        float4 acc[8];
        #pragma unroll
        for (int i = 0; i < 8; i++) {
            acc[i] = (w[i] != 0.0f) ? g_cam4[8*t + i] : z4;
        }
        float rgb[24], d[8], a[8];
        #pragma unroll
        for (int i = 0; i < 8; i++) {
            float wpe = __fadd_rn(w[i], EPS);
            a[i] = fminf(fmaxf(w[i], 0.0f), 1.0f);
            float inv = __fdiv_rn(1.0f, wpe);
            rgb[3*i+0] = __fmul_rn(__fmul_rn(acc[i].x, inv), a[i]);
            rgb[3*i+1] = __fmul_rn(__fmul_rn(acc[i].y, inv), a[i]);
            rgb[3*i+2] = __fmul_rn(__fmul_rn(acc[i].z, inv), a[i]);
            d[i] = __fmul_rn(acc[i].w, inv);
        }
        float* rgbp = out + OFF_RGB + 24 * t;
        st_v8(rgbp + 0,  rgb[0],  rgb[1],  rgb[2],  rgb[3],
                         rgb[4],  rgb[5],  rgb[6],  rgb[7]);
        st_v8(rgbp + 8,  rgb[8],  rgb[9],  rgb[10], rgb[11],
                         rgb[12], rgb[13], rgb[14], rgb[15]);
        st_v8(rgbp + 16, rgb[16], rgb[17], rgb[18], rgb[19],
                         rgb[20], rgb[21], rgb[22], rgb[23]);
        st_v8(out + OFF_DEPTH + 8*t, d[0], d[1], d[2], d[3],
                                     d[4], d[5], d[6], d[7]);
        st_v8(out + OFF_ALPHA + 8*t, a[0], a[1], a[2], a[3],
                                     a[4], a[5], a[6], a[7]);
        if (any) {
            st_v8((float*)g_camA4 + 8*t, 0.f, 0.f, 0.f, 0.f,
                                         0.f, 0.f, 0.f, 0.f);
            #pragma unroll
            for (int i = 0; i < 8; i++)
                if (w[i] != 0.0f) g_cam4[8*t + i] = z4;
        }
    } else if (t < CAM_T8 + LID_T8) {
        int j = t - CAM_T8;
        float p[16];
        float* lp = (float*)g_lid4 + 16 * j;
        ld_v8(lp + 0, p + 0);
        ld_v8(lp + 8, p + 8);
        float d[8], w[8];
        #pragma unroll
        for (int i = 0; i < 8; i++) {
            d[i] = __fdiv_rn(p[2*i], __fadd_rn(p[2*i+1], EPS));
            w[i] = fminf(fmaxf(p[2*i+1], 0.0f), 1.0f);
        }
        st_v8(out + OFF_LD + 8*j, d[0], d[1], d[2], d[3],
                                  d[4], d[5], d[6], d[7]);
        st_v8(out + OFF_LA + 8*j, w[0], w[1], w[2], w[3],
                                  w[4], w[5], w[6], w[7]);
        st_v8(lp + 0, 0.f, 0.f, 0.f, 0.f, 0.f, 0.f, 0.f, 0.f);
        st_v8(lp + 8, 0.f, 0.f, 0.f, 0.f, 0.f, 0.f, 0.f, 0.f);
    }
}

extern "C" void kernel_launch(void* const* d_in, const int* in_sizes, int n_in,
                              void* d_out, int out_size) {
    const float* means = (const float*)d_in[0];
    const float* sh    = (const float*)d_in[3];
    const float* opa_c = (const float*)d_in[4];
    const float* opa_l = (const float*)d_in[5];
    const float* c2w   = (const float*)d_in[6];
    const float* K     = (const float*)d_in[7];
    const float* l2w   = (const float*)d_in[8];
    float* out = (float*)d_out;

    int n = in_sizes[0] / 3;

    splat_kernel<<<(n + 255) / 256, 256>>>(means, sh, opa_c, opa_l,
                                           c2w, K, l2w, n);
    int tot = CAM_T8 + LID_T8;
    finalize_kernel<<<(tot + 255) / 256, 256>>>(out);
}